// round 1
// baseline (speedup 1.0000x reference)
#include <cuda_runtime.h>
#include <cstdint>

#define B_ROWS 65536
#define D_IN   256
#define D_G    512
#define VBS    128
#define EPS_BN 1e-5f

#define BM 128
#define BN 128
#define BK 16
#define PAD 4
#define NTHREADS 256

// 128 MB scratch for z = GBN(feat@W^T) * priors  (static device array: allowed)
__device__ float g_z[(size_t)B_ROWS * D_G];

// ---------------------------------------------------------------------------
// Kernel 1: fused SGEMM (C = feat @ W^T) + GhostBatchNorm + gamma/beta + priors
// Block tile: M=128 (exactly one ghost batch) x N=128. Grid: (D_G/BN, B/BM).
// GBN is exact within the block: column mean/var over the block's 128 rows.
// ---------------------------------------------------------------------------
__global__ __launch_bounds__(NTHREADS, 2)
void fused_gemm_gbn(const float* __restrict__ feat,
                    const float* __restrict__ W,
                    const float* __restrict__ priors,
                    const float* __restrict__ gamma,
                    const float* __restrict__ beta)
{
    __shared__ float As[2][BK][BM + PAD];
    __shared__ float Bs[2][BK][BN + PAD];
    __shared__ float cscale[BN];
    __shared__ float cshift[BN];

    const int tid = threadIdx.x;
    const int tx  = tid & 15;       // 0..15 -> column group (8 cols each)
    const int ty  = tid >> 4;       // 0..15 -> row group (8 rows each)
    const int m0  = blockIdx.y * BM;
    const int n0  = blockIdx.x * BN;

    // loader mapping: per pass of 256 threads covers 64 rows x 16 k (as float4)
    const int lm = tid >> 2;        // 0..63
    const int lk = (tid & 3) * 4;   // 0,4,8,12

    float acc[8][8];
#pragma unroll
    for (int i = 0; i < 8; i++)
#pragma unroll
        for (int j = 0; j < 8; j++) acc[i][j] = 0.0f;

    // ---- initial tile (k-block 0) straight to smem buffer 0 ----
#pragma unroll
    for (int it = 0; it < 2; ++it) {
        const int m = it * 64 + lm;
        float4 a = *(const float4*)&feat[(size_t)(m0 + m) * D_IN + lk];
        As[0][lk + 0][m] = a.x; As[0][lk + 1][m] = a.y;
        As[0][lk + 2][m] = a.z; As[0][lk + 3][m] = a.w;
        float4 b = *(const float4*)&W[(size_t)(n0 + m) * D_IN + lk];
        Bs[0][lk + 0][m] = b.x; Bs[0][lk + 1][m] = b.y;
        Bs[0][lk + 2][m] = b.z; Bs[0][lk + 3][m] = b.w;
    }
    __syncthreads();

    const int NT = D_IN / BK;   // 16 k-tiles
    float4 pa[2], pb[2];

    for (int t = 0; t < NT; ++t) {
        const int buf = t & 1;

        if (t + 1 < NT) {
            const int kb = (t + 1) * BK;
#pragma unroll
            for (int it = 0; it < 2; ++it) {
                const int m = it * 64 + lm;
                pa[it] = *(const float4*)&feat[(size_t)(m0 + m) * D_IN + kb + lk];
                pb[it] = *(const float4*)&W[(size_t)(n0 + m) * D_IN + kb + lk];
            }
        }

#pragma unroll
        for (int kk = 0; kk < BK; ++kk) {
            float ar[8], br[8];
            *(float4*)&ar[0] = *(const float4*)&As[buf][kk][ty * 8];
            *(float4*)&ar[4] = *(const float4*)&As[buf][kk][ty * 8 + 4];
            *(float4*)&br[0] = *(const float4*)&Bs[buf][kk][tx * 8];
            *(float4*)&br[4] = *(const float4*)&Bs[buf][kk][tx * 8 + 4];
#pragma unroll
            for (int i = 0; i < 8; i++)
#pragma unroll
                for (int j = 0; j < 8; j++)
                    acc[i][j] = fmaf(ar[i], br[j], acc[i][j]);
        }

        if (t + 1 < NT) {
            const int nb = buf ^ 1;
#pragma unroll
            for (int it = 0; it < 2; ++it) {
                const int m = it * 64 + lm;
                As[nb][lk + 0][m] = pa[it].x; As[nb][lk + 1][m] = pa[it].y;
                As[nb][lk + 2][m] = pa[it].z; As[nb][lk + 3][m] = pa[it].w;
                Bs[nb][lk + 0][m] = pb[it].x; Bs[nb][lk + 1][m] = pb[it].y;
                Bs[nb][lk + 2][m] = pb[it].z; Bs[nb][lk + 3][m] = pb[it].w;
            }
        }
        __syncthreads();
    }

    // ---- Ghost BatchNorm epilogue (reuse smem tiles as reduction scratch) ----
    float* rsum = &As[0][0][0];   // 16 x 128 partial sums   (fits: 4224 floats)
    float* rsq  = &Bs[0][0][0];   // 16 x 128 partial sumsq

#pragma unroll
    for (int j = 0; j < 8; j++) {
        float s = 0.0f, s2 = 0.0f;
#pragma unroll
        for (int i = 0; i < 8; i++) {
            const float v = acc[i][j];
            s += v;
            s2 = fmaf(v, v, s2);
        }
        rsum[ty * BN + tx * 8 + j] = s;
        rsq [ty * BN + tx * 8 + j] = s2;
    }
    __syncthreads();

    if (tid < BN) {
        float s = 0.0f, s2 = 0.0f;
#pragma unroll
        for (int r = 0; r < 16; r++) {
            s  += rsum[r * BN + tid];
            s2 += rsq [r * BN + tid];
        }
        const float mean = s * (1.0f / VBS);
        const float var  = s2 * (1.0f / VBS) - mean * mean;
        const float sc   = gamma[n0 + tid] * rsqrtf(var + EPS_BN);
        cscale[tid] = sc;
        cshift[tid] = beta[n0 + tid] - mean * sc;
    }
    __syncthreads();

    float scl[8], shf[8];
#pragma unroll
    for (int j = 0; j < 8; j++) {
        scl[j] = cscale[tx * 8 + j];
        shf[j] = cshift[tx * 8 + j];
    }

#pragma unroll
    for (int i = 0; i < 8; i++) {
        const int row = m0 + ty * 8 + i;
        const float4* pr = (const float4*)&priors[(size_t)row * D_G + n0 + tx * 8];
        const float4 p0 = pr[0], p1 = pr[1];
        float4 z0, z1;
        z0.x = fmaf(acc[i][0], scl[0], shf[0]) * p0.x;
        z0.y = fmaf(acc[i][1], scl[1], shf[1]) * p0.y;
        z0.z = fmaf(acc[i][2], scl[2], shf[2]) * p0.z;
        z0.w = fmaf(acc[i][3], scl[3], shf[3]) * p0.w;
        z1.x = fmaf(acc[i][4], scl[4], shf[4]) * p1.x;
        z1.y = fmaf(acc[i][5], scl[5], shf[5]) * p1.y;
        z1.z = fmaf(acc[i][6], scl[6], shf[6]) * p1.z;
        z1.w = fmaf(acc[i][7], scl[7], shf[7]) * p1.w;
        float4* zp = (float4*)&g_z[(size_t)row * D_G + n0 + tx * 8];
        zp[0] = z0;
        zp[1] = z1;
    }
}

// ---------------------------------------------------------------------------
// Kernel 2: sparsemax per row (D=512) via Michelot's simplex-projection
// fixed point. One warp per row; 16 values / lane held in registers.
// ---------------------------------------------------------------------------
__global__ __launch_bounds__(256)
void sparsemax_kernel(float* __restrict__ out)
{
    const int gw   = (blockIdx.x * blockDim.x + threadIdx.x) >> 5;
    const int lane = threadIdx.x & 31;
    const float* zr = &g_z[(size_t)gw * D_G];

    float v[16];
#pragma unroll
    for (int i = 0; i < 16; i++) v[i] = zr[i * 32 + lane];

    // shift by row max (matches reference's stabilization)
    float mx = v[0];
#pragma unroll
    for (int i = 1; i < 16; i++) mx = fmaxf(mx, v[i]);
#pragma unroll
    for (int o = 16; o > 0; o >>= 1)
        mx = fmaxf(mx, __shfl_xor_sync(0xffffffffu, mx, o));

    float s = 0.0f;
#pragma unroll
    for (int i = 0; i < 16; i++) { v[i] -= mx; s += v[i]; }
#pragma unroll
    for (int o = 16; o > 0; o >>= 1)
        s += __shfl_xor_sync(0xffffffffu, s, o);

    float tau = (s - 1.0f) * (1.0f / 512.0f);   // first Michelot iterate (full set)

    for (int it = 0; it < 64; ++it) {
        float ns = 0.0f;
        int   k  = 0;
#pragma unroll
        for (int i = 0; i < 16; i++) {
            if (v[i] > tau) { ns += v[i]; k++; }
        }
#pragma unroll
        for (int o = 16; o > 0; o >>= 1) {
            ns += __shfl_xor_sync(0xffffffffu, ns, o);
            k  += __shfl_xor_sync(0xffffffffu, k,  o);
        }
        const float nt = (ns - 1.0f) / (float)k;
        if (nt == tau) break;   // support stable -> exact fixed point
        tau = nt;
    }

    float* orow = out + (size_t)gw * D_G;
#pragma unroll
    for (int i = 0; i < 16; i++)
        orow[i * 32 + lane] = fmaxf(v[i] - tau, 0.0f);
}

// ---------------------------------------------------------------------------
extern "C" void kernel_launch(void* const* d_in, const int* in_sizes, int n_in,
                              void* d_out, int out_size)
{
    const float* priors = (const float*)d_in[0];   // [B, 512]
    const float* feat   = (const float*)d_in[1];   // [B, 256]
    const float* W      = (const float*)d_in[2];   // [512, 256]
    const float* gamma  = (const float*)d_in[3];   // [512]
    const float* beta   = (const float*)d_in[4];   // [512]
    float* out = (float*)d_out;                    // [B, 512]

    dim3 grid1(D_G / BN, B_ROWS / BM);             // (4, 512)
    fused_gemm_gbn<<<grid1, NTHREADS>>>(feat, W, priors, gamma, beta);

    const int warps = B_ROWS;                      // one warp per row
    sparsemax_kernel<<<(warps * 32) / 256, 256>>>(out);
}